// round 8
// baseline (speedup 1.0000x reference)
#include <cuda_runtime.h>
#include <cstdint>

#define N_PRE     50000
#define VEC_DIM   300
#define IN_SIZE   50000
#define N_TOKENS  12800
#define VEC_BYTES 1200            // 300 f32
#define ROW_BYTES 1712            // 428 f32
#define TPB       16              // tokens per block
#define NTHR      128
#define NBLK      (N_TOKENS / TPB)   // 800

static __device__ __forceinline__ uint32_t smem_u32(const void* p) {
    uint32_t a;
    asm("{ .reg .u64 t; cvta.to.shared.u64 t, %1; cvt.u32.u64 %0, t; }"
        : "=r"(a) : "l"(p));
    return a;
}

// Per block: 16 tokens.
//  phase A (warp0): ballot pre-tokens, expect_tx, 16 lanes issue cp.async.bulk
//                   G->S of each pre token's 1200B vector row in parallel.
//  phase B (all 4 warps, overlapped with A's loads): warp w builds hidden
//                   parts (bias [+ scattered W column gather]) and oov zeros
//                   into the smem row buffers via STS.
//  phase C (warp0): wait mbarrier, fence, 16 lanes each bulk-store one 1712B
//                   output row S->G, commit, wait_group 0.
// Result: only the irreducible scattered W gather consumes L1tex wavefronts.
__global__ __launch_bounds__(NTHR) void encoder_kernel(
    const int*    __restrict__ tokens,
    const float*  __restrict__ vectors,   // [N_PRE * 300]
    const float*  __restrict__ W,         // [128, IN_SIZE]
    const float4* __restrict__ b4,        // [32]
    float*        __restrict__ out)       // [N_TOKENS * 428]
{
    __shared__ int stok[TPB];
    __shared__ __align__(8)  unsigned long long mbar;
    __shared__ __align__(16) unsigned char buf[TPB * ROW_BYTES];  // 27392 B

    const int tid  = threadIdx.x;
    const int lane = tid & 31;
    const int warp = tid >> 5;
    const int tbase = blockIdx.x * TPB;

    if (tid < TPB) stok[tid] = __ldg(&tokens[tbase + tid]);
    if (tid == 0) {
        asm volatile("mbarrier.init.shared.b64 [%0], %1;"
                     :: "r"(smem_u32(&mbar)), "r"(1) : "memory");
    }
    __syncthreads();

    const uint32_t mb      = smem_u32(&mbar);
    const uint32_t buf_base = smem_u32(buf);

    // ---- phase A: issue all vector bulk loads (warp 0, 16 lanes in parallel)
    if (tid < 32) {
        const int  tk  = (tid < TPB) ? stok[tid] : 0x7fffffff;
        const bool pre = (tid < TPB) && (tk < N_PRE);
        const unsigned m = __ballot_sync(0xFFFFFFFFu, pre);
        if (tid == 0) {
            asm volatile("mbarrier.arrive.expect_tx.shared.b64 _, [%0], %1;"
                         :: "r"(mb), "r"((unsigned)__popc(m) * VEC_BYTES) : "memory");
        }
        __syncwarp();
        if (pre) {
            const float* src = vectors + (size_t)tk * VEC_DIM;
            asm volatile(
                "cp.async.bulk.shared::cta.global.mbarrier::complete_tx::bytes "
                "[%0], [%1], %2, [%3];"
                :: "r"(buf_base + tid * ROW_BYTES), "l"(src),
                   "r"(VEC_BYTES), "r"(mb) : "memory");
        }
    }

    // ---- phase B: hidden parts + oov zeros (all warps; overlaps phase A)
    const float4 bb = __ldg(&b4[lane]);
    const float4 z  = make_float4(0.f, 0.f, 0.f, 0.f);
    #pragma unroll
    for (int j = 0; j < 4; j++) {
        const int s = 4 * warp + j;
        const int tk = stok[s];
        unsigned char* slotp = buf + (size_t)s * ROW_BYTES;
        if (tk < N_PRE) {
            reinterpret_cast<float4*>(slotp + VEC_BYTES)[lane] = bb;
        } else {
            const int c = tk - N_PRE;
            const float* Wc = W + c + (size_t)(4 * lane) * IN_SIZE;
            float4 h = bb;
            h.x += __ldg(Wc);
            h.y += __ldg(Wc + (size_t)IN_SIZE);
            h.z += __ldg(Wc + (size_t)2 * IN_SIZE);
            h.w += __ldg(Wc + (size_t)3 * IN_SIZE);
            float4* v4 = reinterpret_cast<float4*>(slotp);
            v4[lane] = z; v4[lane + 32] = z;
            if (lane < 11) v4[lane + 64] = z;            // 75 float4 total
            reinterpret_cast<float4*>(slotp + VEC_BYTES)[lane] = h;
        }
    }

    __syncthreads();

    // ---- phase C: wait for vector loads, then bulk-store all 16 rows
    if (tid < 32) {
        uint32_t done;
        asm volatile(
            "{ .reg .pred p;\n"
            "  mbarrier.try_wait.parity.shared.b64 p, [%1], %2;\n"
            "  selp.b32 %0, 1, 0, p; }"
            : "=r"(done) : "r"(mb), "r"(0u) : "memory");
        if (!done) {
            asm volatile(
                "{ .reg .pred P1;\n"
                "WL_%=:\n"
                "  mbarrier.try_wait.parity.shared.b64 P1, [%0], %1;\n"
                "  @P1 bra.uni WD_%=;\n"
                "  bra.uni WL_%=;\n"
                "WD_%=: }"
                :: "r"(mb), "r"(0u) : "memory");
        }
        asm volatile("fence.proxy.async.shared::cta;" ::: "memory");
        if (tid < TPB) {
            float* dst = out + (size_t)(tbase + tid) * 428;
            asm volatile("cp.async.bulk.global.shared::cta.bulk_group [%0], [%1], %2;"
                         :: "l"(dst), "r"(buf_base + tid * ROW_BYTES),
                            "r"(ROW_BYTES) : "memory");
            asm volatile("cp.async.bulk.commit_group;" ::: "memory");
            asm volatile("cp.async.bulk.wait_group 0;" ::: "memory");
        }
    }
}

extern "C" void kernel_launch(void* const* d_in, const int* in_sizes, int n_in,
                              void* d_out, int out_size)
{
    const int*    tokens  = (const int*)   d_in[0];
    const float*  vectors = (const float*) d_in[1];
    const float*  W       = (const float*) d_in[2];
    const float4* b       = (const float4*)d_in[3];
    float*        out     = (float*)       d_out;

    encoder_kernel<<<NBLK, NTHR>>>(tokens, vectors, W, b, out);
}

// round 11
// speedup vs baseline: 1.3740x; 1.3740x over previous
#include <cuda_runtime.h>
#include <cstdint>

#define N_PRE    50000
#define VEC_DIM  300        // 75 float4
#define HIDDEN   128        // 32 float4
#define IN_SIZE  50000
#define OUT_DIM  428        // 107 float4
#define N_TOKENS (64 * 200)

// Cache-policy register: L2 evict_last for the whole access stream.
static __device__ __forceinline__ uint64_t mk_policy_evict_last() {
    uint64_t pol;
    asm volatile("createpolicy.fractional.L2::evict_last.b64 %0, 1.0;"
                 : "=l"(pol));
    return pol;
}
static __device__ __forceinline__ float ldg_el_f32(const float* p, uint64_t pol) {
    float v;
    asm volatile("ld.global.nc.L2::cache_hint.f32 %0, [%1], %2;"
                 : "=f"(v) : "l"(p), "l"(pol));
    return v;
}
static __device__ __forceinline__ float4 ldg_el_f128(const float4* p, uint64_t pol) {
    float4 v;
    asm volatile("ld.global.nc.L2::cache_hint.v4.f32 {%0,%1,%2,%3}, [%4], %5;"
                 : "=f"(v.x), "=f"(v.y), "=f"(v.z), "=f"(v.w)
                 : "l"(p), "l"(pol));
    return v;
}
// streaming store (evict early; don't churn the pinned read set)
static __device__ __forceinline__ void stg_cs_f128(float4* p, float4 v) {
    asm volatile("st.global.cs.v4.f32 [%0], {%1,%2,%3,%4};"
                 :: "l"(p), "f"(v.x), "f"(v.y), "f"(v.z), "f"(v.w) : "memory");
}

// R2 structure (best so far): one 128-thread block per token.
// All W / vector reads carry an L2 evict_last policy so the fixed ~34MB
// touched read set becomes L2-resident across graph replays; output stores .cs.
__global__ __launch_bounds__(128) void encoder_kernel(
    const int*    __restrict__ tokens,    // [N_TOKENS]
    const float4* __restrict__ vectors4,  // [N_PRE * 75]
    const float*  __restrict__ W,         // [HIDDEN, IN_SIZE]
    const float4* __restrict__ b4,        // [32]
    float4*       __restrict__ out4)      // [N_TOKENS * 107]
{
    const int t   = blockIdx.x;
    const int tid = threadIdx.x;
    const int tok = __ldg(&tokens[t]);        // tiny, broadcast

    float4* orow = out4 + (size_t)t * (OUT_DIM / 4);

    if (tok < N_PRE) {
        const uint64_t pol = mk_policy_evict_last();
        const float4* vrow = vectors4 + (size_t)tok * (VEC_DIM / 4);
        if (tid < 75) {
            float4 v = ldg_el_f128(&vrow[tid], pol);
            stg_cs_f128(&orow[tid], v);
        }
        if (tid < 32) {
            float4 bb = __ldg(&b4[tid]);
            stg_cs_f128(&orow[75 + tid], bb);
        }
    } else {
        const float4 z = make_float4(0.f, 0.f, 0.f, 0.f);
        if (tid < 75) stg_cs_f128(&orow[tid], z);
        if (tid < 32) {
            const uint64_t pol = mk_policy_evict_last();
            const int c = tok - N_PRE;
            const float* Wc = W + c + (size_t)(4 * tid) * IN_SIZE;
            // 4 independent evict_last gathers, then one vectorized store
            float w0 = ldg_el_f32(Wc, pol);
            float w1 = ldg_el_f32(Wc + (size_t)IN_SIZE, pol);
            float w2 = ldg_el_f32(Wc + (size_t)2 * IN_SIZE, pol);
            float w3 = ldg_el_f32(Wc + (size_t)3 * IN_SIZE, pol);
            float4 bb = __ldg(&b4[tid]);
            float4 h = make_float4(bb.x + w0, bb.y + w1, bb.z + w2, bb.w + w3);
            stg_cs_f128(&orow[75 + tid], h);
        }
    }
}

extern "C" void kernel_launch(void* const* d_in, const int* in_sizes, int n_in,
                              void* d_out, int out_size)
{
    // metadata order: tokens (int32), vectors (f32), W (f32), b (f32)
    const int*    tokens  = (const int*)   d_in[0];
    const float4* vectors = (const float4*)d_in[1];
    const float*  W       = (const float*) d_in[2];
    const float4* b       = (const float4*)d_in[3];
    float4*       out     = (float4*)      d_out;

    encoder_kernel<<<N_TOKENS, 128>>>(tokens, vectors, W, b, out);
}